// round 8
// baseline (speedup 1.0000x reference)
#include <cuda_runtime.h>

// ---------------------------------------------------------------------------
// OpticalFlowLoss: temporal-loop fused kernel (sm_103a)
// pred, gt: [B=8, T=8, C=3, H=256, W=256] fp32 -> scalar fp32 loss
// One CTA per (batch, 64x16 tile); iterates over the 7 frame pairs with
// double-buffered per-frame smem (gray halos + gt center RGB). Every frame's
// RGB is read from global exactly once per CTA.
// ---------------------------------------------------------------------------

#define B_    8
#define T_    8
#define H_    256
#define W_    256
#define HW_   (H_ * W_)          // 65536
#define FRAME_STRIDE (3 * HW_)

#define TILE_W 64
#define TILE_H 16
#define HROWS  (TILE_H + 2)      // 18 halo rows
#define SCOLS  72                // global cols tileX-4 .. tileX+67
#define SLOTS  (SCOLS / 4)       // 18 float4 slots per row
#define NSLOT  (HROWS * SLOTS)   // 324

#define NBLOCKS ((W_ / TILE_W) * (H_ / TILE_H) * B_)  // 4*16*8 = 512

#define EPSF 1e-3f
#define MEAN_COUNT 7340032.0     // 8*7*2*256*256

__device__ double g_accum;       // zero-init; self-resetting
__device__ unsigned int g_done;  // zero-init; self-resetting

__device__ __forceinline__ float gray3(float r, float g, float b) {
    return 0.2989f * r + 0.587f * g + 0.114f * b;
}

// Sobel + flow for 4 consecutive pixels; gray(t) halo in sc, gray(t+1) in sn.
__device__ __forceinline__ void flow4(
    const float (*sc)[SCOLS], const float (*sn)[SCOLS],
    int ly, int sx, float* u, float* v)
{
    float4 a0 = *(const float4*)&sc[ly    ][sx];
    float4 m0 = *(const float4*)&sc[ly    ][sx + 4];
    float  c0 = sc[ly    ][sx + 8];
    float4 a1 = *(const float4*)&sc[ly + 1][sx];
    float4 m1 = *(const float4*)&sc[ly + 1][sx + 4];
    float  c1 = sc[ly + 1][sx + 8];
    float4 a2 = *(const float4*)&sc[ly + 2][sx];
    float4 m2 = *(const float4*)&sc[ly + 2][sx + 4];
    float  c2 = sc[ly + 2][sx + 8];

    float t0[6] = {a0.w, m0.x, m0.y, m0.z, m0.w, c0};
    float t1[6] = {a1.w, m1.x, m1.y, m1.z, m1.w, c1};
    float t2[6] = {a2.w, m2.x, m2.y, m2.z, m2.w, c2};

    float4 gn = *(const float4*)&sn[ly + 1][sx + 4];  // gray(t+1) center
    float gy2[4] = {gn.x, gn.y, gn.z, gn.w};

    #pragma unroll
    for (int p = 0; p < 4; ++p) {
        float Ix = (t0[p] - t0[p + 2]) + 2.0f * (t1[p] - t1[p + 2])
                 + (t2[p] - t2[p + 2]);
        float Iy = (t0[p] + 2.0f * t0[p + 1] + t0[p + 2])
                 - (t2[p] + 2.0f * t2[p + 1] + t2[p + 2]);
        float It = gy2[p] - t1[p + 1];
        float inv = __fdividef(1.0f, Ix * Ix + Iy * Iy + EPSF);
        u[p] = -Ix * It * inv;
        v[p] = -Iy * It * inv;
    }
}

__global__ __launch_bounds__(256)
void flow_loss_kernel(const float* __restrict__ pred,
                      const float* __restrict__ gt,
                      float* __restrict__ out) {
    const int b = blockIdx.z;
    const int tileX = blockIdx.x * TILE_W;
    const int tileY = blockIdx.y * TILE_H;
    const int baseB = b * T_ * FRAME_STRIDE;

    __shared__ float gP[2][HROWS][SCOLS];           // pred gray halo
    __shared__ float gG[2][HROWS][SCOLS];           // gt   gray halo
    __shared__ float rgbG[2][3][TILE_H][TILE_W];    // gt center RGB (for mm)
    __shared__ float warpSum[8];

    // ---- per-frame loader: gray halos + gt center RGB ----
    auto load_frame = [&](int f, int buf) {
        const int base = baseB + f * FRAME_STRIDE;
        for (int i = threadIdx.x; i < NSLOT; i += 256) {
            int hy = i / SLOTS;             // 0..17
            int sl = i - hy * SLOTS;        // 0..17
            int gh = tileY + hy - 1;
            int gc = tileX - 4 + sl * 4;
            float4 vp = make_float4(0.f, 0.f, 0.f, 0.f);
            float4 vg = vp;
            float4 rg, gg, bg;
            bool in = ((unsigned)gh < H_) && ((unsigned)gc < W_);
            if (in) {
                int off = base + gh * W_ + gc;
                float4 r  = __ldg((const float4*)(pred + off));
                float4 g  = __ldg((const float4*)(pred + off + HW_));
                float4 bb = __ldg((const float4*)(pred + off + 2 * HW_));
                rg = __ldg((const float4*)(gt + off));
                gg = __ldg((const float4*)(gt + off + HW_));
                bg = __ldg((const float4*)(gt + off + 2 * HW_));
                vp = make_float4(gray3(r.x, g.x, bb.x), gray3(r.y, g.y, bb.y),
                                 gray3(r.z, g.z, bb.z), gray3(r.w, g.w, bb.w));
                vg = make_float4(gray3(rg.x, gg.x, bg.x), gray3(rg.y, gg.y, bg.y),
                                 gray3(rg.z, gg.z, bg.z), gray3(rg.w, gg.w, bg.w));
            }
            *(float4*)&gP[buf][hy][sl * 4] = vp;
            *(float4*)&gG[buf][hy][sl * 4] = vg;
            if (hy >= 1 && hy <= TILE_H && sl >= 1 && sl <= 16) {
                int cy = hy - 1, cx = sl * 4 - 4;
                *(float4*)&rgbG[buf][0][cy][cx] = rg;
                *(float4*)&rgbG[buf][1][cy][cx] = gg;
                *(float4*)&rgbG[buf][2][cy][cx] = bg;
            }
        }
    };

    load_frame(0, 0);
    __syncthreads();

    const int ly = threadIdx.x >> 4;        // 0..15 (tile row)
    const int sx = (threadIdx.x & 15) * 4;  // 0..60 (tile-local first col)

    float acc = 0.0f;

    for (int t = 0; t < T_ - 1; ++t) {
        const int cur = t & 1, nxt = cur ^ 1;
        load_frame(t + 1, nxt);
        __syncthreads();

        float uP[4], vP[4], uG[4], vG[4];
        flow4(gP[cur], gP[nxt], ly, sx, uP, vP);
        flow4(gG[cur], gG[nxt], ly, sx, uG, vG);

        float4 r0 = *(const float4*)&rgbG[cur][0][ly][sx];
        float4 g0 = *(const float4*)&rgbG[cur][1][ly][sx];
        float4 b0 = *(const float4*)&rgbG[cur][2][ly][sx];
        float4 r1 = *(const float4*)&rgbG[nxt][0][ly][sx];
        float4 g1 = *(const float4*)&rgbG[nxt][1][ly][sx];
        float4 b1 = *(const float4*)&rgbG[nxt][2][ly][sx];

        float mm0 = (fabsf(r1.x - r0.x) + fabsf(g1.x - g0.x) + fabsf(b1.x - b0.x)) * (1.f/3.f);
        float mm1 = (fabsf(r1.y - r0.y) + fabsf(g1.y - g0.y) + fabsf(b1.y - b0.y)) * (1.f/3.f);
        float mm2 = (fabsf(r1.z - r0.z) + fabsf(g1.z - g0.z) + fabsf(b1.z - b0.z)) * (1.f/3.f);
        float mm3 = (fabsf(r1.w - r0.w) + fabsf(g1.w - g0.w) + fabsf(b1.w - b0.w)) * (1.f/3.f);

        acc += (fabsf(uP[0] - uG[0]) + fabsf(vP[0] - vG[0])) * mm0;
        acc += (fabsf(uP[1] - uG[1]) + fabsf(vP[1] - vG[1])) * mm1;
        acc += (fabsf(uP[2] - uG[2]) + fabsf(vP[2] - vG[2])) * mm2;
        acc += (fabsf(uP[3] - uG[3]) + fabsf(vP[3] - vG[3])) * mm3;

        __syncthreads();  // compute done before buf[cur] is overwritten
    }

    // --- block reduction ---
    #pragma unroll
    for (int s = 16; s > 0; s >>= 1)
        acc += __shfl_xor_sync(0xFFFFFFFFu, acc, s);

    int lane = threadIdx.x & 31;
    int wid  = threadIdx.x >> 5;
    if (lane == 0) warpSum[wid] = acc;
    __syncthreads();

    if (wid == 0 && lane == 0) {
        float v = 0.0f;
        #pragma unroll
        for (int j = 0; j < 8; ++j) v += warpSum[j];
        atomicAdd(&g_accum, (double)v);
        __threadfence();
        unsigned ticket = atomicAdd(&g_done, 1u);
        if (ticket == NBLOCKS - 1) {
            out[0] = (float)(g_accum / MEAN_COUNT);
            g_accum = 0.0;
            __threadfence();
            g_done = 0u;
        }
    }
}

extern "C" void kernel_launch(void* const* d_in, const int* in_sizes, int n_in,
                              void* d_out, int out_size) {
    const float* pred = (const float*)d_in[0];
    const float* gt   = (const float*)d_in[1];
    float* out = (float*)d_out;

    dim3 grid(W_ / TILE_W, H_ / TILE_H, B_);  // (4, 16, 8) = 512 CTAs
    flow_loss_kernel<<<grid, 256>>>(pred, gt, out);
}